// round 8
// baseline (speedup 1.0000x reference)
#include <cuda_runtime.h>
#include <cstdint>

// Problem shape (fixed by the dataset)
#define PK 4
#define PB 4096
#define PT 32
#define PD 128

#define PAIR_ELEMS ((size_t)PK * PB * PT * PT)   // 16,777,216  (64 MB)
#define NBR_ELEMS  ((size_t)PK * PB * PT * PD)   // 67,108,864  (256 MB)

// 256-bit accesses; stores evict-first (written once, never re-read).
__device__ __forceinline__ void ldg8(const float* p, float* v) {
    asm volatile("ld.global.nc.v8.b32 {%0,%1,%2,%3,%4,%5,%6,%7}, [%8];"
                 : "=f"(v[0]), "=f"(v[1]), "=f"(v[2]), "=f"(v[3]),
                   "=f"(v[4]), "=f"(v[5]), "=f"(v[6]), "=f"(v[7])
                 : "l"(p));
}
__device__ __forceinline__ void stg8_evict_first(float* p, const float* v) {
    asm volatile("st.global.L2::evict_first.v8.b32 "
                 "[%0], {%1,%2,%3,%4,%5,%6,%7,%8};"
                 :: "l"(p),
                    "f"(v[0]), "f"(v[1]), "f"(v[2]), "f"(v[3]),
                    "f"(v[4]), "f"(v[5]), "f"(v[6]), "f"(v[7])
                 : "memory");
}

// One CTA = 2 adjacent anchors (kb0, kb0+1). Warps 0-1 own anchor 0,
// warps 2-3 own anchor 1. All four output regions get 8 KB contiguous
// writes per CTA (DRAM row-buffer locality; half as many write streams).
__global__ __launch_bounds__(128) void distance_layer_kernel(
    const float* __restrict__ semb,     // [K,B,D]
    const int*   __restrict__ slabels,  // [K,B]
    const int*   __restrict__ topk,     // [K,B,T]
    float* __restrict__ pos_out,        // [K,B,T,T]
    float* __restrict__ neg_out,        // [K,B,T,T]
    float* __restrict__ msk_out,        // [K,B,T,T]
    float* __restrict__ nbr_out)        // [K,B,T,D]
{
    const int kb0  = blockIdx.x * 2;    // first anchor (same domain as kb0+1)
    const int k    = kb0 >> 12;         // B = 4096
    const int tid  = threadIdx.x;       // 0..127
    const int warp = tid >> 5;
    const int lane = tid & 31;
    const int half = lane >> 4;         // which of 2 rows this half-warp owns
    const int l16  = lane & 15;         // position within a 512B row
    const int aw   = warp >> 1;         // this warp's anchor (0 or 1)

    __shared__ float s_nsim[2 * PT];
    __shared__ int   s_same[2 * PT];
    __shared__ int   s_idx[2 * PT];

    const float* semb_k = semb + (size_t)k * PB * PD;
    const int    b0     = kb0 & (PB - 1);

    // This warp's anchor embedding: dims [l16*8, l16*8+8)
    float a8[8];
    ldg8(semb_k + (size_t)(b0 + aw) * PD + l16 * 8, a8);

    // Neighbor indices + same-label bits for both anchors (64 entries)
    if (tid < 2 * PT) {
        const int aj  = tid >> 5;                    // anchor 0/1
        const int idx = topk[((size_t)(kb0 + aj)) * PT + (tid & 31)];
        s_idx[tid]  = idx;
        s_same[tid] = (slabels[k * PB + idx] == slabels[kb0 + aj]) ? 1 : 0;
    }
    __syncthreads();

    // ---- Gather phase: 4 warps x (8 iters x 2 rows) = 64 rows ------------
    // Row t in [0,64): anchor = t>>5; warp w covers t in [w*16, w*16+16),
    // so each warp's rows all belong to its fixed anchor aw.
    float* nbr_base = nbr_out + (size_t)kb0 * PT * PD;   // 2 anchors contiguous
    #pragma unroll
    for (int i = 0; i < 8; ++i) {
        const int t = warp * 16 + i * 2 + half;
        float v[8];
        ldg8(semb_k + (size_t)s_idx[t] * PD + l16 * 8, v);
        stg8_evict_first(nbr_base + t * PD + l16 * 8, v);
        float p = v[0]*a8[0] + v[1]*a8[1] + v[2]*a8[2] + v[3]*a8[3]
                + v[4]*a8[4] + v[5]*a8[5] + v[6]*a8[6] + v[7]*a8[7];
        #pragma unroll
        for (int off = 8; off; off >>= 1)
            p += __shfl_xor_sync(0xffffffffu, p, off);
        if (l16 == 0) s_nsim[t] = p;
    }
    __syncthreads();

    // ---- Pair phase: per anchor, 1024 floats = 128 float8 per tensor -----
    float* pos_base = pos_out + (size_t)kb0 * PT * PT;
    float* neg_base = neg_out + (size_t)kb0 * PT * PT;
    float* msk_base = msk_out + (size_t)kb0 * PT * PT;

    const int s  = tid >> 2;            // 0..31
    const int d0 = (tid & 3) << 3;      // 0,8,16,24

    #pragma unroll
    for (int j = 0; j < 2; ++j) {
        const int   base = j * PT;
        const int   ss   = s_same[base + s];
        const float ns   = s_nsim[base + s];

        float pv[8], nv[8], mv[8];
        #pragma unroll
        for (int q = 0; q < 8; ++q) {
            const int m = ss & (s_same[base + d0 + q] ^ 1);
            mv[q] = (float)m;
            pv[q] = m ? ns : 0.0f;
            nv[q] = m ? s_nsim[base + d0 + q] : 0.0f;
        }
        const int off = j * PT * PT + tid * 8;
        stg8_evict_first(pos_base + off, pv);
        stg8_evict_first(neg_base + off, nv);
        stg8_evict_first(msk_base + off, mv);
    }
}

extern "C" void kernel_launch(void* const* d_in, const int* in_sizes, int n_in,
                              void* d_out, int out_size)
{
    (void)in_sizes; (void)n_in; (void)out_size;

    const float* semb    = (const float*)d_in[0];
    const int*   slabels = (const int*)  d_in[1];
    const int*   topk    = (const int*)  d_in[2];

    float* out = (float*)d_out;
    float* pos = out;
    float* neg = out + PAIR_ELEMS;
    float* msk = out + 2 * PAIR_ELEMS;
    float* nbr = out + 3 * PAIR_ELEMS;

    dim3 grid(PK * PB / 2);   // 8192 CTAs, 2 anchors each
    dim3 block(128);
    distance_layer_kernel<<<grid, block>>>(semb, slabels, topk,
                                           pos, neg, msk, nbr);
}